// round 5
// baseline (speedup 1.0000x reference)
#include <cuda_runtime.h>
#include <math.h>

// Problem constants
#define BQ 512
#define TQ 8192
#define KW 5

// Chunked-speculative scan parameters
#define CE 128              // emitted steps per chunk (64 chunks/row, 2 warps/row)
#define CW 224              // warm-up steps; proven flip-free margin (R2)
#define W  16               // staged tile width
#define NT ((CW + CE) / W)  // 22 tiles
#define ET (CW / W)         // 14 = first emitting tile
#define PIN 20              // staging pitch (words): conflict-free quarter-warp LDS.128
#define PSAL 129            // sal row pitch (words): conflict-free scalar access

// One LIF step, all 3 channels. Explicit rn mul/add (no FMA contraction) to
// match the reference arithmetic bit-for-bit (validated rel_err 0.0 twice).
#define STEP1(x0, x1, x2, OUT)                                              \
    {                                                                       \
        v0 = __fadd_rn(__fmul_rn(d0, v0), (x0));                            \
        v1 = __fadd_rn(__fmul_rn(d1, v1), (x1));                            \
        v2 = __fadd_rn(__fmul_rn(d2, v2), (x2));                            \
        float s0_ = (v0 >= 1.0f) ? 1.0f : 0.0f;                             \
        float s1_ = (v1 >= 1.0f) ? 1.0f : 0.0f;                             \
        float s2_ = (v2 >= 1.0f) ? 1.0f : 0.0f;                             \
        v0 = __fadd_rn(v0, -s0_);                                           \
        v1 = __fadd_rn(v1, -s1_);                                           \
        v2 = __fadd_rn(v2, -s2_);                                           \
        (OUT) = __fadd_rn(__fadd_rn(__fmul_rn(w0, s0_), __fmul_rn(w1, s1_)),\
                          __fmul_rn(w2, s2_));                              \
    }

// Sorted top-5 insert of key (rarely taken).
#define TOP5_INS(KEY)                                                       \
    if ((KEY) > k4) {                                                       \
        k4 = (KEY);                                                         \
        if (k4 > k3) { unsigned long long t_ = k3; k3 = k4; k4 = t_; }      \
        if (k3 > k2) { unsigned long long t_ = k2; k2 = k3; k3 = t_; }      \
        if (k2 > k1) { unsigned long long t_ = k1; k1 = k2; k2 = t_; }      \
        if (k1 > k0) { unsigned long long t_ = k0; k0 = k1; k1 = t_; }      \
    }

// Coalesced tile load: 32 segments of 16 floats (64B, line-contained),
// lane covers segment (i*8 + lane/4), float4 (lane&3).
#define LDG_TILE(J)                                                         \
    do {                                                                    \
        const int tb = (J) * W - CW + woff;                                 \
        _Pragma("unroll")                                                   \
        for (int i = 0; i < 4; i++) {                                       \
            int g = (((i << 3) + sseg) << 7) + tb + f4;                     \
            if (g < 0) g = 0;  /* chunk-0 warm garbage; state reset at ET */\
            rb0[i] = *(const float4*)(pr0 + g);                             \
            rb1[i] = *(const float4*)(pr1 + g);                             \
            rb2[i] = *(const float4*)(pr2 + g);                             \
        }                                                                   \
    } while (0)

#define STS_TILE()                                                          \
    do {                                                                    \
        _Pragma("unroll")                                                   \
        for (int i = 0; i < 4; i++) {                                       \
            int s = (i << 3) + sseg;                                        \
            *(float4*)&stg[(0 * 32 + s) * PIN + f4] = rb0[i];               \
            *(float4*)&stg[(1 * 32 + s) * PIN + f4] = rb1[i];               \
            *(float4*)&stg[(2 * 32 + s) * PIN + f4] = rb2[i];               \
        }                                                                   \
    } while (0)

__global__ __launch_bounds__(64)
void fused_spike_kernel(const float* __restrict__ amp,
                        const float* __restrict__ pitch,
                        const float* __restrict__ bnd,
                        const float* __restrict__ decay,
                        const float* __restrict__ wts,
                        float* __restrict__ out)
{
    __shared__ float s_stg[2 * 3 * 32 * PIN];    // 15360 B
    __shared__ float s_sal[2 * 32 * PSAL];       // 33024 B
    __shared__ unsigned long long s_merge[2][KW];
    __shared__ float s_recip;

    const int lane = threadIdx.x & 31;
    const int w    = threadIdx.x >> 5;       // warp: half-row (chunks w*32 ..)
    const int b    = blockIdx.x;             // row
    const int woff = w << 12;                // 4096: warp's t offset in row

    const float d0 = decay[0], d1 = decay[1], d2 = decay[2];
    const float w0 = wts[0],   w1 = wts[1],   w2 = wts[2];

    const float* pr0 = amp   + (size_t)b * TQ;
    const float* pr1 = pitch + (size_t)b * TQ;
    const float* pr2 = bnd   + (size_t)b * TQ;

    float* stg = s_stg + w * (3 * 32 * PIN);
    float* sal = s_sal + w * (32 * PSAL);

    const int sseg = lane >> 2;       // segment sub-index 0..7
    const int f4   = (lane & 3) << 2; // float offset within 16-float segment

    // lane's chunk staging rows
    const int c0 = (0 * 32 + lane) * PIN;
    const int c1 = (1 * 32 + lane) * PIN;
    const int c2 = (2 * 32 + lane) * PIN;

    float4 rb0[4], rb1[4], rb2[4];
    float v0 = 0.f, v1 = 0.f, v2 = 0.f;
    unsigned long long k0 = 0, k1 = 0, k2 = 0, k3 = 0, k4 = 0;

    LDG_TILE(0);

    #pragma unroll 1
    for (int j = 0; j < NT; j++) {
        STS_TILE();
        __syncwarp();
        if (j + 1 < NT) LDG_TILE(j + 1);   // prefetch overlaps scan

        if (j == ET && w == 0 && lane == 0) { v0 = 0.f; v1 = 0.f; v2 = 0.f; }

        if (j >= ET) {
            float* sd = sal + lane * PSAL + (j - ET) * W;
            const int tg = woff + lane * CE + (j - ET) * W;  // global t of step 0
            #pragma unroll
            for (int t = 0; t < W; t += 4) {
                float4 xa = *(const float4*)&stg[c0 + t];
                float4 xp = *(const float4*)&stg[c1 + t];
                float4 xb = *(const float4*)&stg[c2 + t];
                float o;
                unsigned long long key;
                STEP1(xa.x, xp.x, xb.x, o); sd[t + 0] = o;
                key = ((unsigned long long)__float_as_uint(o) << 32)
                      | (unsigned)(TQ - 1 - (tg + t + 0));
                TOP5_INS(key);
                STEP1(xa.y, xp.y, xb.y, o); sd[t + 1] = o;
                key = ((unsigned long long)__float_as_uint(o) << 32)
                      | (unsigned)(TQ - 1 - (tg + t + 1));
                TOP5_INS(key);
                STEP1(xa.z, xp.z, xb.z, o); sd[t + 2] = o;
                key = ((unsigned long long)__float_as_uint(o) << 32)
                      | (unsigned)(TQ - 1 - (tg + t + 2));
                TOP5_INS(key);
                STEP1(xa.w, xp.w, xb.w, o); sd[t + 3] = o;
                key = ((unsigned long long)__float_as_uint(o) << 32)
                      | (unsigned)(TQ - 1 - (tg + t + 3));
                TOP5_INS(key);
            }
        } else {
            #pragma unroll
            for (int t = 0; t < W; t += 4) {
                float4 xa = *(const float4*)&stg[c0 + t];
                float4 xp = *(const float4*)&stg[c1 + t];
                float4 xb = *(const float4*)&stg[c2 + t];
                float o;
                STEP1(xa.x, xp.x, xb.x, o);
                STEP1(xa.y, xp.y, xb.y, o);
                STEP1(xa.z, xp.z, xb.z, o);
                STEP1(xa.w, xp.w, xb.w, o);
                (void)o;
            }
        }
        __syncwarp();
    }

    // ---- warp merge: 5 rounds of warp-max with owner pop (keys unique) ----
    {
        int p = 0;
        #pragma unroll
        for (int k = 0; k < KW; k++) {
            unsigned long long cand =
                (p == 0) ? k0 : (p == 1) ? k1 : (p == 2) ? k2 :
                (p == 3) ? k3 : (p == 4) ? k4 : 0ull;
            unsigned long long m = cand;
            #pragma unroll
            for (int o = 16; o; o >>= 1) {
                unsigned long long x = __shfl_xor_sync(0xffffffffu, m, o);
                if (x > m) m = x;
            }
            if (cand == m) p++;
            if (lane == 0) s_merge[w][k] = m;
        }
    }
    __syncthreads();

    // ---- cross-warp merge + scalar outputs (thread 0) ----
    if (threadIdx.x == 0) {
        unsigned long long win[KW];
        int ia = 0, ib = 0;
        #pragma unroll
        for (int k = 0; k < KW; k++) {
            unsigned long long a = (ia < KW) ? s_merge[0][ia] : 0ull;
            unsigned long long c = (ib < KW) ? s_merge[1][ib] : 0ull;
            if (a >= c) { win[k] = a; ia++; } else { win[k] = c; ib++; }
        }
        const float maxv  = __uint_as_float((unsigned)(win[0] >> 32));
        const float recip = 1.0f / (maxv + 1e-6f);
        s_recip = recip;

        float acc = 0.f;
        #pragma unroll
        for (int k = 0; k < KW; k++)
            acc += __uint_as_float((unsigned)(win[k] >> 32)) * recip;
        out[b] = 0.5f + 2.0f * tanhf(1.8f * (acc / 5.0f));

        float* oi = out + BQ + (size_t)BQ * TQ + (size_t)b * KW;
        #pragma unroll
        for (int k = 0; k < KW; k++)
            oi[k] = (float)(TQ - 1 - (int)(unsigned)(win[k] & 0xffffffffu));
    }
    __syncthreads();

    // ---- normalize + store this warp's 4096 sal values -------------------
    // Scalar, alignment-safe: lane handles t = q*32 + lane (q = 0..127).
    //   chunk c = q>>2, in-chunk s = (q&3)*32 + lane
    //   LDS bank = (c*129 + s) % 32 = (c + lane) % 32 -> conflict-free
    //   STG: 32 consecutive floats -> 128B coalesced
    const float recip = s_recip;
    float* go = out + BQ + (size_t)b * TQ + woff;
    #pragma unroll 8
    for (int q = 0; q < 128; q++) {
        int c = q >> 2;
        int s = ((q & 3) << 5) + lane;
        go[(q << 5) + lane] = sal[c * PSAL + s] * recip;
    }
}

extern "C" void kernel_launch(void* const* d_in, const int* in_sizes, int n_in,
                              void* d_out, int out_size)
{
    const float* amp   = (const float*)d_in[0];
    const float* pitch = (const float*)d_in[1];
    const float* bnd   = (const float*)d_in[2];
    const float* decay = (const float*)d_in[3];
    const float* wts   = (const float*)d_in[4];
    float* out = (float*)d_out;

    fused_spike_kernel<<<BQ, 64>>>(amp, pitch, bnd, decay, wts, out);
}

// round 6
// speedup vs baseline: 1.0557x; 1.0557x over previous
#include <cuda_runtime.h>
#include <math.h>

// Problem constants
#define BQ 512
#define TQ 8192
#define KW 5

// Chunked-speculative scan parameters (accuracy-proven: CE=128/CW=224)
#define CE 128              // emitted steps per chunk
#define CW 224              // warm-up steps
#define W  16               // staged tile width
#define NT ((CW + CE) / W)  // 22 tiles
#define ET (CW / W)         // 14 = first emitting tile
#define PIN 20              // staging pitch (words): conflict-free quarter-warp LDS.128
#define PSAL 129            // sal row pitch (words): conflict-free scalar access

#define STG_WORDS (3 * 32 * PIN)   // 1920 per warp
#define SAL_WORDS (32 * PSAL)      // 4128 per warp
#define SMEM_DYN ((4 * STG_WORDS + 4 * SAL_WORDS) * 4)  // 96768 B

// One LIF step, all 3 channels. u = d*v + x (rn mul+add, matches reference
// bitwise); v_next = p ? u-1 : u  ==  u - s*theta exactly (s*theta in {0,1}).
#define STEP1(x0, x1, x2, OUT)                                              \
    {                                                                       \
        float u0 = __fadd_rn(__fmul_rn(d0, v0), (x0));                      \
        float u1 = __fadd_rn(__fmul_rn(d1, v1), (x1));                      \
        float u2 = __fadd_rn(__fmul_rn(d2, v2), (x2));                      \
        bool p0 = (u0 >= 1.0f), p1 = (u1 >= 1.0f), p2 = (u2 >= 1.0f);       \
        v0 = p0 ? __fadd_rn(u0, -1.0f) : u0;                                \
        v1 = p1 ? __fadd_rn(u1, -1.0f) : u1;                                \
        v2 = p2 ? __fadd_rn(u2, -1.0f) : u2;                                \
        float s0_ = p0 ? 1.0f : 0.0f;                                       \
        float s1_ = p1 ? 1.0f : 0.0f;                                       \
        float s2_ = p2 ? 1.0f : 0.0f;                                       \
        (OUT) = __fadd_rn(__fadd_rn(__fmul_rn(w0, s0_), __fmul_rn(w1, s1_)),\
                          __fmul_rn(w2, s2_));                              \
    }

// Warm variant: state update only.
#define STEPW(x0, x1, x2)                                                   \
    {                                                                       \
        float u0 = __fadd_rn(__fmul_rn(d0, v0), (x0));                      \
        float u1 = __fadd_rn(__fmul_rn(d1, v1), (x1));                      \
        float u2 = __fadd_rn(__fmul_rn(d2, v2), (x2));                      \
        v0 = (u0 >= 1.0f) ? __fadd_rn(u0, -1.0f) : u0;                      \
        v1 = (u1 >= 1.0f) ? __fadd_rn(u1, -1.0f) : u1;                      \
        v2 = (u2 >= 1.0f) ? __fadd_rn(u2, -1.0f) : u2;                      \
    }

// Sorted top-5 insert of key (rarely taken).
#define TOP5_INS(KEY)                                                       \
    if ((KEY) > k4) {                                                       \
        k4 = (KEY);                                                         \
        if (k4 > k3) { unsigned long long t_ = k3; k3 = k4; k4 = t_; }      \
        if (k3 > k2) { unsigned long long t_ = k2; k2 = k3; k3 = t_; }      \
        if (k2 > k1) { unsigned long long t_ = k1; k1 = k2; k2 = t_; }      \
        if (k1 > k0) { unsigned long long t_ = k0; k0 = k1; k1 = t_; }      \
    }

// Coalesced tile load: 32 segments of 16 floats (64B, line-contained).
#define LDG_TILE(J)                                                         \
    do {                                                                    \
        const int tb = (J) * W - CW + woff;                                 \
        _Pragma("unroll")                                                   \
        for (int i = 0; i < 4; i++) {                                       \
            int g = (((i << 3) + sseg) << 7) + tb + f4;                     \
            if (g < 0) g = 0;  /* chunk-0 warm garbage; state reset at ET */\
            rb0[i] = *(const float4*)(pr0 + g);                             \
            rb1[i] = *(const float4*)(pr1 + g);                             \
            rb2[i] = *(const float4*)(pr2 + g);                             \
        }                                                                   \
    } while (0)

#define STS_TILE()                                                          \
    do {                                                                    \
        _Pragma("unroll")                                                   \
        for (int i = 0; i < 4; i++) {                                       \
            int s = (i << 3) + sseg;                                        \
            *(float4*)&stg[(0 * 32 + s) * PIN + f4] = rb0[i];               \
            *(float4*)&stg[(1 * 32 + s) * PIN + f4] = rb1[i];               \
            *(float4*)&stg[(2 * 32 + s) * PIN + f4] = rb2[i];               \
        }                                                                   \
    } while (0)

__global__ __launch_bounds__(128)
void fused_spike_kernel(const float* __restrict__ amp,
                        const float* __restrict__ pitch,
                        const float* __restrict__ bnd,
                        const float* __restrict__ decay,
                        const float* __restrict__ wts,
                        float* __restrict__ out)
{
    extern __shared__ float sm[];
    __shared__ unsigned long long s_merge[4][KW];
    __shared__ float s_recip[2];

    const int lane = threadIdx.x & 31;
    const int w    = threadIdx.x >> 5;        // 0..3
    const int rl   = w >> 1;                  // row within block (0..1)
    const int half = w & 1;                   // half-row (chunk group)
    const int b    = blockIdx.x * 2 + rl;     // global row
    const int woff = half << 12;              // 4096: warp's t offset in row

    const float d0 = decay[0], d1 = decay[1], d2 = decay[2];
    const float w0 = wts[0],   w1 = wts[1],   w2 = wts[2];

    const float* pr0 = amp   + (size_t)b * TQ;
    const float* pr1 = pitch + (size_t)b * TQ;
    const float* pr2 = bnd   + (size_t)b * TQ;

    float* stg = sm + w * STG_WORDS;
    float* sal = sm + 4 * STG_WORDS + w * SAL_WORDS;

    const int sseg = lane >> 2;       // segment sub-index 0..7
    const int f4   = (lane & 3) << 2; // float offset within 16-float segment

    const int c0 = (0 * 32 + lane) * PIN;
    const int c1 = (1 * 32 + lane) * PIN;
    const int c2 = (2 * 32 + lane) * PIN;

    float4 rb0[4], rb1[4], rb2[4];
    float v0 = 0.f, v1 = 0.f, v2 = 0.f;
    unsigned long long k0 = 0, k1 = 0, k2 = 0, k3 = 0, k4 = 0;

    LDG_TILE(0);

    #pragma unroll 1
    for (int j = 0; j < NT; j++) {
        STS_TILE();
        __syncwarp();
        if (j + 1 < NT) LDG_TILE(j + 1);   // prefetch overlaps scan

        if (j == ET && half == 0 && lane == 0) { v0 = 0.f; v1 = 0.f; v2 = 0.f; }

        // software-pipelined LDS: group t+4 loads before group t is scanned
        float4 xa = *(const float4*)&stg[c0];
        float4 xp = *(const float4*)&stg[c1];
        float4 xb = *(const float4*)&stg[c2];

        if (j >= ET) {
            float* sd = sal + lane * PSAL + (j - ET) * W;
            const int tg = woff + lane * CE + (j - ET) * W;
            #pragma unroll
            for (int t = 0; t < W; t += 4) {
                float4 na, np_, nb;
                if (t + 4 < W) {
                    na  = *(const float4*)&stg[c0 + t + 4];
                    np_ = *(const float4*)&stg[c1 + t + 4];
                    nb  = *(const float4*)&stg[c2 + t + 4];
                }
                float o;
                unsigned long long key;
                STEP1(xa.x, xp.x, xb.x, o); sd[t + 0] = o;
                key = ((unsigned long long)__float_as_uint(o) << 32)
                      | (unsigned)(TQ - 1 - (tg + t + 0));
                TOP5_INS(key);
                STEP1(xa.y, xp.y, xb.y, o); sd[t + 1] = o;
                key = ((unsigned long long)__float_as_uint(o) << 32)
                      | (unsigned)(TQ - 1 - (tg + t + 1));
                TOP5_INS(key);
                STEP1(xa.z, xp.z, xb.z, o); sd[t + 2] = o;
                key = ((unsigned long long)__float_as_uint(o) << 32)
                      | (unsigned)(TQ - 1 - (tg + t + 2));
                TOP5_INS(key);
                STEP1(xa.w, xp.w, xb.w, o); sd[t + 3] = o;
                key = ((unsigned long long)__float_as_uint(o) << 32)
                      | (unsigned)(TQ - 1 - (tg + t + 3));
                TOP5_INS(key);
                xa = na; xp = np_; xb = nb;
            }
        } else {
            #pragma unroll
            for (int t = 0; t < W; t += 4) {
                float4 na, np_, nb;
                if (t + 4 < W) {
                    na  = *(const float4*)&stg[c0 + t + 4];
                    np_ = *(const float4*)&stg[c1 + t + 4];
                    nb  = *(const float4*)&stg[c2 + t + 4];
                }
                STEPW(xa.x, xp.x, xb.x);
                STEPW(xa.y, xp.y, xb.y);
                STEPW(xa.z, xp.z, xb.z);
                STEPW(xa.w, xp.w, xb.w);
                xa = na; xp = np_; xb = nb;
            }
        }
        __syncwarp();
    }

    // ---- warp merge: 5 rounds of warp-max with owner pop (keys unique) ----
    {
        int p = 0;
        #pragma unroll
        for (int k = 0; k < KW; k++) {
            unsigned long long cand =
                (p == 0) ? k0 : (p == 1) ? k1 : (p == 2) ? k2 :
                (p == 3) ? k3 : (p == 4) ? k4 : 0ull;
            unsigned long long m = cand;
            #pragma unroll
            for (int o = 16; o; o >>= 1) {
                unsigned long long x = __shfl_xor_sync(0xffffffffu, m, o);
                if (x > m) m = x;
            }
            if (cand == m) p++;
            if (lane == 0) s_merge[w][k] = m;
        }
    }
    __syncthreads();

    // ---- per-row cross-warp merge + scalar outputs ----
    if ((threadIdx.x & 63) == 0) {
        const int r = threadIdx.x >> 6;          // row within block
        const int gb = blockIdx.x * 2 + r;
        unsigned long long win[KW];
        int ia = 0, ib = 0;
        #pragma unroll
        for (int k = 0; k < KW; k++) {
            unsigned long long a = (ia < KW) ? s_merge[2 * r][ia] : 0ull;
            unsigned long long c = (ib < KW) ? s_merge[2 * r + 1][ib] : 0ull;
            if (a >= c) { win[k] = a; ia++; } else { win[k] = c; ib++; }
        }
        const float maxv  = __uint_as_float((unsigned)(win[0] >> 32));
        const float recip = 1.0f / (maxv + 1e-6f);
        s_recip[r] = recip;

        float acc = 0.f;
        #pragma unroll
        for (int k = 0; k < KW; k++)
            acc += __uint_as_float((unsigned)(win[k] >> 32)) * recip;
        out[gb] = 0.5f + 2.0f * tanhf(1.8f * (acc / 5.0f));

        float* oi = out + BQ + (size_t)BQ * TQ + (size_t)gb * KW;
        #pragma unroll
        for (int k = 0; k < KW; k++)
            oi[k] = (float)(TQ - 1 - (int)(unsigned)(win[k] & 0xffffffffu));
    }
    __syncthreads();

    // ---- normalize + store this warp's 4096 sal values -------------------
    // Scalar, alignment-safe, conflict-free, coalesced (validated in R5).
    const float recip = s_recip[rl];
    float* go = out + BQ + (size_t)b * TQ + woff;
    #pragma unroll 8
    for (int q = 0; q < 128; q++) {
        int cc = q >> 2;
        int ss = ((q & 3) << 5) + lane;
        go[(q << 5) + lane] = sal[cc * PSAL + ss] * recip;
    }
}

extern "C" void kernel_launch(void* const* d_in, const int* in_sizes, int n_in,
                              void* d_out, int out_size)
{
    const float* amp   = (const float*)d_in[0];
    const float* pitch = (const float*)d_in[1];
    const float* bnd   = (const float*)d_in[2];
    const float* decay = (const float*)d_in[3];
    const float* wts   = (const float*)d_in[4];
    float* out = (float*)d_out;

    cudaFuncSetAttribute(fused_spike_kernel,
                         cudaFuncAttributeMaxDynamicSharedMemorySize,
                         SMEM_DYN);

    fused_spike_kernel<<<BQ / 2, 128, SMEM_DYN>>>(amp, pitch, bnd, decay, wts, out);
}